// round 13
// baseline (speedup 1.0000x reference)
#include <cuda_runtime.h>

// Problem dims (fixed by the reference)
#define B_DIM 256
#define N_DIM 4096
#define KC    128           // C*M = 8*16 reduction length
#define TPB   512           // one block per batch row; each thread owns 8 consecutive n
#define GRID  B_DIM
#define STRIDE (N_DIM / 4)  // float4 stride per k

__global__ __launch_bounds__(TPB, 2)
void fused_conv_argmax_kernel(const float* __restrict__ x,
                              const float* __restrict__ W,
                              const float* __restrict__ r_target,
                              const float* __restrict__ d_target,
                              float* __restrict__ out) {
    const int b = blockIdx.x;       // one block per batch row
    const int t = threadIdx.x;

    // Each thread owns 8 consecutive n; the block covers the full 4096-wide
    // row, so the k-loop walks a contiguous 2MB region in ascending address
    // order. W is a uniform broadcast LDG per iteration (L1-resident, 512B).
    const int n0 = t * 8;
    const float4* xp = reinterpret_cast<const float4*>(
        x + (size_t)b * (KC * (size_t)N_DIM) + n0);

    float a0x = 0.f, a0y = 0.f, a0z = 0.f, a0w = 0.f;
    float a1x = 0.f, a1y = 0.f, a1z = 0.f, a1w = 0.f;

    // depth-2 software pipeline: keep next iteration's loads in flight
    // across unroll-group seams.
    float4 p0 = __ldcs(&xp[0]);
    float4 p1 = __ldcs(&xp[1]);
#pragma unroll 4
    for (int k = 0; k < KC; k++) {
        float4 c0 = p0, c1 = p1;
        if (k + 1 < KC) {
            p0 = __ldcs(&xp[(k + 1) * STRIDE]);
            p1 = __ldcs(&xp[(k + 1) * STRIDE + 1]);
        }
        float wk = __ldg(&W[k]);                       // uniform broadcast
        a0x = fmaf(c0.x, wk, a0x);
        a0y = fmaf(c0.y, wk, a0y);
        a0z = fmaf(c0.z, wk, a0z);
        a0w = fmaf(c0.w, wk, a0w);
        a1x = fmaf(c1.x, wk, a1x);
        a1y = fmaf(c1.y, wk, a1y);
        a1z = fmaf(c1.z, wk, a1z);
        a1w = fmaf(c1.w, wk, a1w);
    }

    // write outputs, streaming (evict-first) in both L1 and L2
    float* orow = out + (size_t)b * N_DIM;
    __stcs(reinterpret_cast<float4*>(orow + n0),     make_float4(a0x, a0y, a0z, a0w));
    __stcs(reinterpret_cast<float4*>(orow + n0 + 4), make_float4(a1x, a1y, a1z, a1w));

    // thread-local argmax, ascending n -> first-occurrence tie-break.
    float bv = a0x; int bi = n0;
    if (a0y > bv) { bv = a0y; bi = n0 + 1; }
    if (a0z > bv) { bv = a0z; bi = n0 + 2; }
    if (a0w > bv) { bv = a0w; bi = n0 + 3; }
    if (a1x > bv) { bv = a1x; bi = n0 + 4; }
    if (a1y > bv) { bv = a1y; bi = n0 + 5; }
    if (a1z > bv) { bv = a1z; bi = n0 + 6; }
    if (a1w > bv) { bv = a1w; bi = n0 + 7; }

    // warp reduce (value, index), tie -> lower index
#pragma unroll
    for (int off = 16; off; off >>= 1) {
        float ov = __shfl_down_sync(0xffffffffu, bv, off);
        int   oi = __shfl_down_sync(0xffffffffu, bi, off);
        if (ov > bv || (ov == bv && oi < bi)) { bv = ov; bi = oi; }
    }

    __shared__ float sv[TPB / 32];
    __shared__ int   si[TPB / 32];
    const int warp = t >> 5, lane = t & 31;
    if (lane == 0) { sv[warp] = bv; si[warp] = bi; }
    __syncthreads();

    // Block b holds the FINAL argmax for row b (SPLIT=1): write its own
    // tail elements directly — no cross-block sync, no global scratch.
    if (t == 0) {
        bv = sv[0]; bi = si[0];
#pragma unroll
        for (int i = 1; i < TPB / 32; i++) {
            if (sv[i] > bv || (sv[i] == bv && si[i] < bi)) { bv = sv[i]; bi = si[i]; }
        }

        // r_index = idx // 64 ; d_index = idx % 64
        const int r_index = bi >> 6;
        const int d_index = bi & 63;
        // astype(int64) truncates toward zero
        const float rv = (float)(int)__ldg(&r_target[r_index]);
        const float dv = (float)(int)__ldg(&d_target[d_index]);

        const size_t base = (size_t)B_DIM * N_DIM;   // after outputs
        out[base +             b] = dv;              // d
        out[base + B_DIM +     b] = rv;              // r (inside tuple)
        out[base + 2 * B_DIM + b] = dv;              // d (inside tuple)
    }
}

extern "C" void kernel_launch(void* const* d_in, const int* in_sizes, int n_in,
                              void* d_out, int out_size) {
    const float* x        = (const float*)d_in[0];  // [256,8,16,4096]
    const float* W        = (const float*)d_in[1];  // [1,8,16,1] -> 128 floats
    const float* r_target = (const float*)d_in[2];  // [64]
    const float* d_target = (const float*)d_in[3];  // [64]
    float* out = (float*)d_out;

    fused_conv_argmax_kernel<<<GRID, TPB>>>(x, W, r_target, d_target, out);
}

// round 14
// speedup vs baseline: 1.0345x; 1.0345x over previous
#include <cuda_runtime.h>

// Problem dims (fixed by the reference)
#define B_DIM 256
#define N_DIM 4096
#define KC    128           // C*M = 8*16 reduction length
#define TPB   512           // one block per batch row; each thread owns 8 consecutive n
#define GRID  B_DIM

__global__ __launch_bounds__(TPB, 2)
void fused_conv_argmax_kernel(const float* __restrict__ x,
                              const float* __restrict__ W,
                              const float* __restrict__ r_target,
                              const float* __restrict__ d_target,
                              float* __restrict__ out) {
    const int b = blockIdx.x;       // one block per batch row
    const int t = threadIdx.x;

    // Each thread owns 8 consecutive n; the block covers the full 4096-wide
    // row, so the k-loop walks a contiguous 2MB region in ascending address
    // order (x[b][k][n] is contiguous in (k,n)). W is read with a uniform
    // broadcast LDG per iteration (L1-resident, 512B total) — no smem
    // staging, no __syncthreads before the stream starts.
    const int n0 = t * 8;
    const float4* xp = reinterpret_cast<const float4*>(
        x + (size_t)b * (KC * (size_t)N_DIM) + n0);

    float a0x = 0.f, a0y = 0.f, a0z = 0.f, a0w = 0.f;
    float a1x = 0.f, a1y = 0.f, a1z = 0.f, a1w = 0.f;
#pragma unroll 4
    for (int k = 0; k < KC; k++) {
        float4 v0 = __ldcs(&xp[k * (N_DIM / 4)]);      // n0..n0+3
        float4 v1 = __ldcs(&xp[k * (N_DIM / 4) + 1]);  // n0+4..n0+7
        float wk = __ldg(&W[k]);                       // uniform broadcast
        a0x = fmaf(v0.x, wk, a0x);
        a0y = fmaf(v0.y, wk, a0y);
        a0z = fmaf(v0.z, wk, a0z);
        a0w = fmaf(v0.w, wk, a0w);
        a1x = fmaf(v1.x, wk, a1x);
        a1y = fmaf(v1.y, wk, a1y);
        a1z = fmaf(v1.z, wk, a1z);
        a1w = fmaf(v1.w, wk, a1w);
    }

    // write outputs, bypassing L1 (streaming store)
    float* orow = out + (size_t)b * N_DIM;
    __stcg(reinterpret_cast<float4*>(orow + n0),     make_float4(a0x, a0y, a0z, a0w));
    __stcg(reinterpret_cast<float4*>(orow + n0 + 4), make_float4(a1x, a1y, a1z, a1w));

    // thread-local argmax, ascending n -> first-occurrence tie-break.
    float bv = a0x; int bi = n0;
    if (a0y > bv) { bv = a0y; bi = n0 + 1; }
    if (a0z > bv) { bv = a0z; bi = n0 + 2; }
    if (a0w > bv) { bv = a0w; bi = n0 + 3; }
    if (a1x > bv) { bv = a1x; bi = n0 + 4; }
    if (a1y > bv) { bv = a1y; bi = n0 + 5; }
    if (a1z > bv) { bv = a1z; bi = n0 + 6; }
    if (a1w > bv) { bv = a1w; bi = n0 + 7; }

    // warp reduce (value, index), tie -> lower index
#pragma unroll
    for (int off = 16; off; off >>= 1) {
        float ov = __shfl_down_sync(0xffffffffu, bv, off);
        int   oi = __shfl_down_sync(0xffffffffu, bi, off);
        if (ov > bv || (ov == bv && oi < bi)) { bv = ov; bi = oi; }
    }

    __shared__ float sv[TPB / 32];
    __shared__ int   si[TPB / 32];
    const int warp = t >> 5, lane = t & 31;
    if (lane == 0) { sv[warp] = bv; si[warp] = bi; }
    __syncthreads();

    // Block b holds the FINAL argmax for row b (SPLIT=1): write its own
    // tail elements directly — no cross-block sync, no global scratch.
    if (t == 0) {
        bv = sv[0]; bi = si[0];
#pragma unroll
        for (int i = 1; i < TPB / 32; i++) {
            if (sv[i] > bv || (sv[i] == bv && si[i] < bi)) { bv = sv[i]; bi = si[i]; }
        }

        // r_index = idx // 64 ; d_index = idx % 64
        const int r_index = bi >> 6;
        const int d_index = bi & 63;
        // astype(int64) truncates toward zero
        const float rv = (float)(int)__ldg(&r_target[r_index]);
        const float dv = (float)(int)__ldg(&d_target[d_index]);

        const size_t base = (size_t)B_DIM * N_DIM;   // after outputs
        out[base +             b] = dv;              // d
        out[base + B_DIM +     b] = rv;              // r (inside tuple)
        out[base + 2 * B_DIM + b] = dv;              // d (inside tuple)
    }
}

extern "C" void kernel_launch(void* const* d_in, const int* in_sizes, int n_in,
                              void* d_out, int out_size) {
    const float* x        = (const float*)d_in[0];  // [256,8,16,4096]
    const float* W        = (const float*)d_in[1];  // [1,8,16,1] -> 128 floats
    const float* r_target = (const float*)d_in[2];  // [64]
    const float* d_target = (const float*)d_in[3];  // [64]
    float* out = (float*)d_out;

    fused_conv_argmax_kernel<<<GRID, TPB>>>(x, W, r_target, d_target, out);
}